// round 1
// baseline (speedup 1.0000x reference)
#include <cuda_runtime.h>
#include <cuda_bf16.h>
#include <cstdint>

// Problem constants
#define B_  2
#define S_  2048
#define E_  1024
#define H_  16
#define DH_ 64
#define HD_ 1024          // H*Dh
#define M_  (B_*S_)       // 4096 rows for all GEMMs

// ---------------------------------------------------------------------------
// Scratch (no cudaMalloc allowed): Q, K, V projections and attention output Z
// Each 4096 x 1024 fp32 = 16 MB; total 64 MB static device memory.
// ---------------------------------------------------------------------------
__device__ float g_Q[M_ * HD_];
__device__ float g_K[M_ * HD_];
__device__ float g_V[M_ * HD_];
__device__ float g_Z[M_ * HD_];

// ---------------------------------------------------------------------------
// FP32 SGEMM + bias: C[M,N] = A[M,K] @ W[K,N] + b[N]
// 128x128 block tile, BK=16, 256 threads, 8x8 per-thread micro-tile.
// ---------------------------------------------------------------------------
__global__ void __launch_bounds__(256)
sgemm_bias_kernel(const float* __restrict__ A,
                  const float* __restrict__ W,
                  const float* __restrict__ bias,
                  float* __restrict__ C,
                  int M, int N, int K)
{
    const int BK = 16;
    __shared__ float As[16][132];   // [k][m], padded to dodge conflicts
    __shared__ float Ws[16][132];   // [k][n]

    const int tid  = threadIdx.x;
    const int row0 = blockIdx.y * 128;
    const int col0 = blockIdx.x * 128;
    const int tx = tid & 15;        // col group (0..15)
    const int ty = tid >> 4;        // row group (0..15)

    float acc[8][8];
    #pragma unroll
    for (int i = 0; i < 8; i++)
        #pragma unroll
        for (int j = 0; j < 8; j++) acc[i][j] = 0.f;

    for (int k0 = 0; k0 < K; k0 += BK) {
        // Load A tile: 128 rows x 16 cols = 512 float4; 2 per thread.
        // Load W tile: 16 rows x 128 cols = 512 float4; 2 per thread.
        #pragma unroll
        for (int t = 0; t < 2; t++) {
            int idx = tid + t * 256;
            int ar  = idx >> 2;                 // 0..127
            int ac4 = idx & 3;                  // 0..3
            float4 av = *(const float4*)&A[(size_t)(row0 + ar) * K + k0 + ac4 * 4];
            As[ac4 * 4 + 0][ar] = av.x;
            As[ac4 * 4 + 1][ar] = av.y;
            As[ac4 * 4 + 2][ar] = av.z;
            As[ac4 * 4 + 3][ar] = av.w;

            int wr  = idx >> 5;                 // 0..15
            int wc4 = idx & 31;                 // 0..31
            *(float4*)&Ws[wr][wc4 * 4] =
                *(const float4*)&W[(size_t)(k0 + wr) * N + col0 + wc4 * 4];
        }
        __syncthreads();

        #pragma unroll
        for (int k = 0; k < BK; k++) {
            float4 a0 = *(const float4*)&As[k][ty * 8];
            float4 a1 = *(const float4*)&As[k][ty * 8 + 4];
            float4 w0 = *(const float4*)&Ws[k][tx * 8];
            float4 w1 = *(const float4*)&Ws[k][tx * 8 + 4];
            float a[8] = {a0.x, a0.y, a0.z, a0.w, a1.x, a1.y, a1.z, a1.w};
            float w[8] = {w0.x, w0.y, w0.z, w0.w, w1.x, w1.y, w1.z, w1.w};
            #pragma unroll
            for (int i = 0; i < 8; i++)
                #pragma unroll
                for (int j = 0; j < 8; j++)
                    acc[i][j] += a[i] * w[j];
        }
        __syncthreads();
    }

    #pragma unroll
    for (int i = 0; i < 8; i++) {
        int r = row0 + ty * 8 + i;
        #pragma unroll
        for (int j4 = 0; j4 < 2; j4++) {
            int c = col0 + tx * 8 + j4 * 4;
            float4 bv = *(const float4*)&bias[c];
            float4 out;
            out.x = acc[i][j4 * 4 + 0] + bv.x;
            out.y = acc[i][j4 * 4 + 1] + bv.y;
            out.z = acc[i][j4 * 4 + 2] + bv.z;
            out.w = acc[i][j4 * 4 + 3] + bv.w;
            *(float4*)&C[(size_t)r * N + c] = out;
        }
    }
}

// ---------------------------------------------------------------------------
// Causal flash attention, fp32, online softmax.
// One thread = one query row. Block = 128 rows. K/V tiles of 64 rows in SMEM.
// Q/K/V/Z layout: [B, S, H*Dh]; head h occupies columns [h*64, h*64+64).
// grid = (S/128, H, B), block = 128 threads.
// ---------------------------------------------------------------------------
__global__ void __launch_bounds__(128)
flash_attn_kernel(const float* __restrict__ Q,
                  const float* __restrict__ K,
                  const float* __restrict__ V,
                  float* __restrict__ Z)
{
    __shared__ float4 Ks[64 * 16];   // 64 keys x 64 floats
    __shared__ float4 Vs[64 * 16];

    const int b = blockIdx.z;
    const int h = blockIdx.y;
    const int r = blockIdx.x * 128 + threadIdx.x;   // query index in sequence
    const size_t base = (size_t)b * S_ * HD_ + (size_t)h * DH_;

    // Load q row into registers (64 floats)
    float4 q[16];
    const float4* qrow = (const float4*)&Q[base + (size_t)r * HD_];
    #pragma unroll
    for (int i = 0; i < 16; i++) q[i] = qrow[i];

    float4 o[16];
    #pragma unroll
    for (int i = 0; i < 16; i++) o[i] = make_float4(0.f, 0.f, 0.f, 0.f);
    float m = -1e30f, l = 0.f;

    const int nt = blockIdx.x * 2 + 2;  // key tiles needed (causal)
    for (int kt = 0; kt < nt; kt++) {
        const int k0 = kt * 64;
        // cooperative tile load: 64 rows x 16 float4 = 1024 float4, 8/thread
        #pragma unroll
        for (int t = 0; t < 8; t++) {
            int idx = threadIdx.x + t * 128;
            int kr = idx >> 4;
            int c  = idx & 15;
            Ks[idx] = *(const float4*)&K[base + (size_t)(k0 + kr) * HD_ + c * 4];
            Vs[idx] = *(const float4*)&V[base + (size_t)(k0 + kr) * HD_ + c * 4];
        }
        __syncthreads();

        const int jmax = min(64, r - k0 + 1);   // causal: keys <= r
        for (int j = 0; j < jmax; j++) {
            // q . k_j with 4 independent accumulation chains
            float s0 = 0.f, s1 = 0.f, s2 = 0.f, s3 = 0.f;
            const float4* kr4 = &Ks[j * 16];
            #pragma unroll
            for (int i = 0; i < 16; i++) {
                float4 kk = kr4[i];
                s0 += q[i].x * kk.x;
                s1 += q[i].y * kk.y;
                s2 += q[i].z * kk.z;
                s3 += q[i].w * kk.w;
            }
            float s = ((s0 + s1) + (s2 + s3)) * 0.125f;  // 1/sqrt(64)

            if (s > m) {                 // rare rescale path
                float cr = __expf(m - s);
                l *= cr;
                #pragma unroll
                for (int i = 0; i < 16; i++) {
                    o[i].x *= cr; o[i].y *= cr; o[i].z *= cr; o[i].w *= cr;
                }
                m = s;
            }
            float p = __expf(s - m);
            l += p;
            const float4* vr4 = &Vs[j * 16];
            #pragma unroll
            for (int i = 0; i < 16; i++) {
                float4 vv = vr4[i];
                o[i].x += p * vv.x; o[i].y += p * vv.y;
                o[i].z += p * vv.z; o[i].w += p * vv.w;
            }
        }
        __syncthreads();
    }

    const float inv = 1.f / l;
    float4* zrow = (float4*)&Z[base + (size_t)r * HD_];
    #pragma unroll
    for (int i = 0; i < 16; i++) {
        float4 ov = o[i];
        ov.x *= inv; ov.y *= inv; ov.z *= inv; ov.w *= inv;
        zrow[i] = ov;
    }
}

// ---------------------------------------------------------------------------
// Launch: 3 projection GEMMs -> flash attention -> output GEMM
// Inputs (metadata order): query, key_, value, mask, WQ, bQ, WK, bK, WV, bV, WO, bO
// mask is the exact causal tril -> implemented analytically, input ignored.
// ---------------------------------------------------------------------------
extern "C" void kernel_launch(void* const* d_in, const int* in_sizes, int n_in,
                              void* d_out, int out_size)
{
    const float* query = (const float*)d_in[0];
    const float* key_  = (const float*)d_in[1];
    const float* value = (const float*)d_in[2];
    const float* WQ = (const float*)d_in[4];
    const float* bQ = (const float*)d_in[5];
    const float* WK = (const float*)d_in[6];
    const float* bK = (const float*)d_in[7];
    const float* WV = (const float*)d_in[8];
    const float* bV = (const float*)d_in[9];
    const float* WO = (const float*)d_in[10];
    const float* bO = (const float*)d_in[11];
    float* out = (float*)d_out;

    float *gq, *gk, *gv, *gz;
    cudaGetSymbolAddress((void**)&gq, g_Q);
    cudaGetSymbolAddress((void**)&gk, g_K);
    cudaGetSymbolAddress((void**)&gv, g_V);
    cudaGetSymbolAddress((void**)&gz, g_Z);

    dim3 gemm_grid(HD_ / 128, M_ / 128);   // (8, 32)
    dim3 gemm_block(256);

    sgemm_bias_kernel<<<gemm_grid, gemm_block>>>(query, WQ, bQ, gq, M_, HD_, E_);
    sgemm_bias_kernel<<<gemm_grid, gemm_block>>>(key_,  WK, bK, gk, M_, HD_, E_);
    sgemm_bias_kernel<<<gemm_grid, gemm_block>>>(value, WV, bV, gv, M_, HD_, E_);

    dim3 attn_grid(S_ / 128, H_, B_);      // (16, 16, 2)
    flash_attn_kernel<<<attn_grid, 128>>>(gq, gk, gv, gz);

    dim3 out_grid(E_ / 128, M_ / 128);
    sgemm_bias_kernel<<<out_grid, gemm_block>>>(gz, WO, bO, out, M_, E_, HD_);
}

// round 3
// speedup vs baseline: 1.2913x; 1.2913x over previous
#include <cuda_runtime.h>
#include <cuda_bf16.h>
#include <cstdint>

// Problem constants
#define B_  2
#define S_  2048
#define E_  1024
#define H_  16
#define DH_ 64
#define HD_ 1024          // H*Dh
#define M_  (B_*S_)       // 4096 rows for all GEMMs
#define K_GEMM 1024
#define N_GEMM 1024

// ---------------------------------------------------------------------------
// Scratch (no cudaMalloc allowed)
// ---------------------------------------------------------------------------
__device__ float g_Q[M_ * HD_];
__device__ float g_K[M_ * HD_];
__device__ float g_V[M_ * HD_];
__device__ float g_Z[M_ * HD_];
__device__ __nv_bfloat16 g_Ahi[M_ * K_GEMM];      // split activations
__device__ __nv_bfloat16 g_Alo[M_ * K_GEMM];
__device__ __nv_bfloat16 g_W1t[N_GEMM * K_GEMM];  // transposed+split weights [N][K]
__device__ __nv_bfloat16 g_W2t[N_GEMM * K_GEMM];

__device__ __forceinline__ uint32_t smem_u32(const void* p) {
    uint32_t a;
    asm("{ .reg .u64 t; cvta.to.shared.u64 t, %1; cvt.u32.u64 %0, t; }" : "=r"(a) : "l"(p));
    return a;
}

#define LDSM4(r0, r1, r2, r3, addr) \
    asm volatile("ldmatrix.sync.aligned.m8n8.x4.shared.b16 {%0,%1,%2,%3}, [%4];" \
                 : "=r"(r0), "=r"(r1), "=r"(r2), "=r"(r3) : "r"(addr))

#define MMA16816(d, a, b) \
    asm volatile("mma.sync.aligned.m16n8k16.row.col.f32.bf16.bf16.f32 " \
                 "{%0,%1,%2,%3}, {%4,%5,%6,%7}, {%8,%9}, {%0,%1,%2,%3};" \
                 : "+f"((d)[0]), "+f"((d)[1]), "+f"((d)[2]), "+f"((d)[3]) \
                 : "r"((a)[0]), "r"((a)[1]), "r"((a)[2]), "r"((a)[3]), \
                   "r"((b)[0]), "r"((b)[1]))

// ---------------------------------------------------------------------------
// Split fp32 -> (hi, lo) bf16, elementwise. n4 = elements/4.
// ---------------------------------------------------------------------------
__global__ void __launch_bounds__(256)
split_bf16_kernel(const float* __restrict__ x,
                  __nv_bfloat16* __restrict__ hi,
                  __nv_bfloat16* __restrict__ lo, int n4)
{
    int i = blockIdx.x * blockDim.x + threadIdx.x;
    if (i >= n4) return;
    float4 v = ((const float4*)x)[i];
    __nv_bfloat16 h0 = __float2bfloat16(v.x);
    __nv_bfloat16 h1 = __float2bfloat16(v.y);
    __nv_bfloat16 h2 = __float2bfloat16(v.z);
    __nv_bfloat16 h3 = __float2bfloat16(v.w);
    __nv_bfloat16 l0 = __float2bfloat16(v.x - __bfloat162float(h0));
    __nv_bfloat16 l1 = __float2bfloat16(v.y - __bfloat162float(h1));
    __nv_bfloat16 l2 = __float2bfloat16(v.z - __bfloat162float(h2));
    __nv_bfloat16 l3 = __float2bfloat16(v.w - __bfloat162float(h3));
    __nv_bfloat162 hv0 = {h0, h1}, hv1 = {h2, h3};
    __nv_bfloat162 lv0 = {l0, l1}, lv1 = {l2, l3};
    uint2 hp, lp;
    hp.x = *(uint32_t*)&hv0; hp.y = *(uint32_t*)&hv1;
    lp.x = *(uint32_t*)&lv0; lp.y = *(uint32_t*)&lv1;
    ((uint2*)hi)[i] = hp;
    ((uint2*)lo)[i] = lp;
}

// ---------------------------------------------------------------------------
// Weight prep: W[K][N] fp32 -> W1t/W2t [N][K] bf16 (transpose + split)
// block (32,8), grid (N/32, K/32)
// ---------------------------------------------------------------------------
__global__ void __launch_bounds__(256)
prep_w_kernel(const float* __restrict__ W,
              __nv_bfloat16* __restrict__ w1t,
              __nv_bfloat16* __restrict__ w2t)
{
    __shared__ float t[32][33];
    int n0 = blockIdx.x * 32, k0 = blockIdx.y * 32;
    int tx = threadIdx.x, ty = threadIdx.y;
    #pragma unroll
    for (int i = 0; i < 4; i++)
        t[ty + 8 * i][tx] = W[(size_t)(k0 + ty + 8 * i) * N_GEMM + n0 + tx];
    __syncthreads();
    #pragma unroll
    for (int i = 0; i < 4; i++) {
        float v = t[tx][ty + 8 * i];                 // = W[k0+tx][n0+ty+8i]
        __nv_bfloat16 h = __float2bfloat16(v);
        __nv_bfloat16 l = __float2bfloat16(v - __bfloat162float(h));
        size_t o = (size_t)(n0 + ty + 8 * i) * K_GEMM + k0 + tx;
        w1t[o] = h;
        w2t[o] = l;
    }
}

// ---------------------------------------------------------------------------
// HMMA bf16x3 GEMM: C[M,1024] = (Ahi+Alo) @ (W1t+W2t)^T + bias
// CTA 128x128, BK=32, 8 warps (4M x 2N), warp tile 32x64.
// SMEM rows padded to 80B -> conflict-free STS.128 and ldmatrix.
// grid (N/128, M/128), 256 threads.
// ---------------------------------------------------------------------------
#define LDP 80           // padded row stride in bytes (32 bf16 = 64B data)
#define TILE_B (128 * LDP)

__global__ void __launch_bounds__(256)
gemm_bf16x3_mma(const __nv_bfloat16* __restrict__ Ahi,
                const __nv_bfloat16* __restrict__ Alo,
                const __nv_bfloat16* __restrict__ W1t,
                const __nv_bfloat16* __restrict__ W2t,
                const float* __restrict__ bias,
                float* __restrict__ C)
{
    __shared__ __align__(16) char smem[4 * TILE_B];   // A1 | A2 | W1 | W2
    const uint32_t sb = smem_u32(smem);
    const uint32_t sA1 = sb, sA2 = sb + TILE_B, sW1 = sb + 2 * TILE_B, sW2 = sb + 3 * TILE_B;

    const int tid = threadIdx.x;
    const int wid = tid >> 5, lane = tid & 31;
    const int n0 = blockIdx.x * 128, m0 = blockIdx.y * 128;
    const int mw = (wid & 3) * 32;     // warp m offset in tile
    const int nw = (wid >> 2) * 64;    // warp n offset in tile

    float acc[2][8][4];
    #pragma unroll
    for (int mi = 0; mi < 2; mi++)
        #pragma unroll
        for (int ni = 0; ni < 8; ni++)
            #pragma unroll
            for (int r = 0; r < 4; r++) acc[mi][ni][r] = 0.f;

    // per-thread load slots: idx = tid + t*256, row = idx>>2, cc = idx&3
    const int row_[2] = { tid >> 2, (tid + 256) >> 2 };
    const int cc_[2]  = { tid & 3, (tid + 256) & 3 };

    const __nv_bfloat16* gA1 = Ahi + (size_t)m0 * K_GEMM;
    const __nv_bfloat16* gA2 = Alo + (size_t)m0 * K_GEMM;
    const __nv_bfloat16* gW1 = W1t + (size_t)n0 * K_GEMM;
    const __nv_bfloat16* gW2 = W2t + (size_t)n0 * K_GEMM;

    // load chunk 0
    #pragma unroll
    for (int t = 0; t < 2; t++) {
        int row = row_[t], cc = cc_[t];
        size_t go = (size_t)row * K_GEMM + cc * 8;
        uint32_t so = row * LDP + cc * 16;
        *(float4*)(smem + (sA1 - sb) + so) = *(const float4*)&gA1[go];
        *(float4*)(smem + (sA2 - sb) + so) = *(const float4*)&gA2[go];
        *(float4*)(smem + (sW1 - sb) + so) = *(const float4*)&gW1[go];
        *(float4*)(smem + (sW2 - sb) + so) = *(const float4*)&gW2[go];
    }

    // ldmatrix lane addressing
    const uint32_t a_row = mw + (lane & 15);
    const uint32_t a_kadd = (lane >> 4) << 4;              // +16B for k8-15 half
    const uint32_t b_rowbase = nw + (lane & 7) + (((lane >> 4) & 1) << 3);
    const uint32_t b_kadd = ((lane >> 3) & 1) << 4;

    const int NCHUNK = K_GEMM / 32;    // 32
    float4 pf[4][2];

    for (int c = 0; c < NCHUNK; c++) {
        __syncthreads();

        if (c + 1 < NCHUNK) {
            int k0n = (c + 1) * 32;
            #pragma unroll
            for (int t = 0; t < 2; t++) {
                int row = row_[t], cc = cc_[t];
                size_t go = (size_t)row * K_GEMM + k0n + cc * 8;
                pf[0][t] = *(const float4*)&gA1[go];
                pf[1][t] = *(const float4*)&gA2[go];
                pf[2][t] = *(const float4*)&gW1[go];
                pf[3][t] = *(const float4*)&gW2[go];
            }
        }

        #pragma unroll
        for (int s = 0; s < 2; s++) {
            const uint32_t kb = s * 32;   // byte offset of k16 slice within row
            uint32_t a1f[2][4], a2f[2][4];
            #pragma unroll
            for (int mi = 0; mi < 2; mi++) {
                uint32_t addr1 = sA1 + (a_row + mi * 16) * LDP + kb + a_kadd;
                uint32_t addr2 = sA2 + (a_row + mi * 16) * LDP + kb + a_kadd;
                LDSM4(a1f[mi][0], a1f[mi][1], a1f[mi][2], a1f[mi][3], addr1);
                LDSM4(a2f[mi][0], a2f[mi][1], a2f[mi][2], a2f[mi][3], addr2);
            }
            uint32_t b1f[8][2], b2f[8][2];
            #pragma unroll
            for (int g = 0; g < 4; g++) {   // each covers n16 = 2 n8 tiles
                uint32_t addr1 = sW1 + (b_rowbase + g * 16) * LDP + kb + b_kadd;
                uint32_t addr2 = sW2 + (b_rowbase + g * 16) * LDP + kb + b_kadd;
                LDSM4(b1f[2*g][0], b1f[2*g][1], b1f[2*g+1][0], b1f[2*g+1][1], addr1);
                LDSM4(b2f[2*g][0], b2f[2*g][1], b2f[2*g+1][0], b2f[2*g+1][1], addr2);
            }
            #pragma unroll
            for (int mi = 0; mi < 2; mi++)
                #pragma unroll
                for (int ni = 0; ni < 8; ni++) {
                    MMA16816(acc[mi][ni], a1f[mi], b1f[ni]);
                    MMA16816(acc[mi][ni], a1f[mi], b2f[ni]);
                    MMA16816(acc[mi][ni], a2f[mi], b1f[ni]);
                }
        }

        __syncthreads();

        if (c + 1 < NCHUNK) {
            #pragma unroll
            for (int t = 0; t < 2; t++) {
                int row = row_[t], cc = cc_[t];
                uint32_t so = row * LDP + cc * 16;
                *(float4*)(smem + 0 * TILE_B + so) = pf[0][t];
                *(float4*)(smem + 1 * TILE_B + so) = pf[1][t];
                *(float4*)(smem + 2 * TILE_B + so) = pf[2][t];
                *(float4*)(smem + 3 * TILE_B + so) = pf[3][t];
            }
        }
    }

    // Epilogue: acc -> C with bias. Thread owns (row = lane/4, col = lane%4*2).
    const int erow = m0 + mw + (lane >> 2);
    const int ecol0 = n0 + nw + (lane & 3) * 2;
    #pragma unroll
    for (int mi = 0; mi < 2; mi++) {
        #pragma unroll
        for (int ni = 0; ni < 8; ni++) {
            int col = ecol0 + ni * 8;
            float b0 = bias[col], b1 = bias[col + 1];
            int r0 = erow + mi * 16;
            float2 v0 = { acc[mi][ni][0] + b0, acc[mi][ni][1] + b1 };
            float2 v1 = { acc[mi][ni][2] + b0, acc[mi][ni][3] + b1 };
            *(float2*)&C[(size_t)r0 * N_GEMM + col] = v0;
            *(float2*)&C[(size_t)(r0 + 8) * N_GEMM + col] = v1;
        }
    }
}

// ---------------------------------------------------------------------------
// Causal flash attention, fp32, online softmax (unchanged).
// ---------------------------------------------------------------------------
__global__ void __launch_bounds__(128)
flash_attn_kernel(const float* __restrict__ Q,
                  const float* __restrict__ K,
                  const float* __restrict__ V,
                  float* __restrict__ Z)
{
    __shared__ float4 Ks[64 * 16];
    __shared__ float4 Vs[64 * 16];

    const int b = blockIdx.z;
    const int h = blockIdx.y;
    const int r = blockIdx.x * 128 + threadIdx.x;
    const size_t base = (size_t)b * S_ * HD_ + (size_t)h * DH_;

    float4 q[16];
    const float4* qrow = (const float4*)&Q[base + (size_t)r * HD_];
    #pragma unroll
    for (int i = 0; i < 16; i++) q[i] = qrow[i];

    float4 o[16];
    #pragma unroll
    for (int i = 0; i < 16; i++) o[i] = make_float4(0.f, 0.f, 0.f, 0.f);
    float m = -1e30f, l = 0.f;

    const int nt = blockIdx.x * 2 + 2;
    for (int kt = 0; kt < nt; kt++) {
        const int k0 = kt * 64;
        #pragma unroll
        for (int t = 0; t < 8; t++) {
            int idx = threadIdx.x + t * 128;
            int kr = idx >> 4;
            int c  = idx & 15;
            Ks[idx] = *(const float4*)&K[base + (size_t)(k0 + kr) * HD_ + c * 4];
            Vs[idx] = *(const float4*)&V[base + (size_t)(k0 + kr) * HD_ + c * 4];
        }
        __syncthreads();

        const int jmax = min(64, r - k0 + 1);
        for (int j = 0; j < jmax; j++) {
            float s0 = 0.f, s1 = 0.f, s2 = 0.f, s3 = 0.f;
            const float4* kr4 = &Ks[j * 16];
            #pragma unroll
            for (int i = 0; i < 16; i++) {
                float4 kk = kr4[i];
                s0 += q[i].x * kk.x;
                s1 += q[i].y * kk.y;
                s2 += q[i].z * kk.z;
                s3 += q[i].w * kk.w;
            }
            float s = ((s0 + s1) + (s2 + s3)) * 0.125f;

            if (s > m) {
                float cr = __expf(m - s);
                l *= cr;
                #pragma unroll
                for (int i = 0; i < 16; i++) {
                    o[i].x *= cr; o[i].y *= cr; o[i].z *= cr; o[i].w *= cr;
                }
                m = s;
            }
            float p = __expf(s - m);
            l += p;
            const float4* vr4 = &Vs[j * 16];
            #pragma unroll
            for (int i = 0; i < 16; i++) {
                float4 vv = vr4[i];
                o[i].x += p * vv.x; o[i].y += p * vv.y;
                o[i].z += p * vv.z; o[i].w += p * vv.w;
            }
        }
        __syncthreads();
    }

    const float inv = 1.f / l;
    float4* zrow = (float4*)&Z[base + (size_t)r * HD_];
    #pragma unroll
    for (int i = 0; i < 16; i++) {
        float4 ov = o[i];
        ov.x *= inv; ov.y *= inv; ov.z *= inv; ov.w *= inv;
        zrow[i] = ov;
    }
}

// ---------------------------------------------------------------------------
// Launch
// ---------------------------------------------------------------------------
extern "C" void kernel_launch(void* const* d_in, const int* in_sizes, int n_in,
                              void* d_out, int out_size)
{
    const float* query = (const float*)d_in[0];
    const float* key_  = (const float*)d_in[1];
    const float* value = (const float*)d_in[2];
    const float* WQ = (const float*)d_in[4];
    const float* bQ = (const float*)d_in[5];
    const float* WK = (const float*)d_in[6];
    const float* bK = (const float*)d_in[7];
    const float* WV = (const float*)d_in[8];
    const float* bV = (const float*)d_in[9];
    const float* WO = (const float*)d_in[10];
    const float* bO = (const float*)d_in[11];
    float* out = (float*)d_out;

    float *gq, *gk, *gv, *gz;
    __nv_bfloat16 *ahi, *alo, *w1t, *w2t;
    cudaGetSymbolAddress((void**)&gq, g_Q);
    cudaGetSymbolAddress((void**)&gk, g_K);
    cudaGetSymbolAddress((void**)&gv, g_V);
    cudaGetSymbolAddress((void**)&gz, g_Z);
    cudaGetSymbolAddress((void**)&ahi, g_Ahi);
    cudaGetSymbolAddress((void**)&alo, g_Alo);
    cudaGetSymbolAddress((void**)&w1t, g_W1t);
    cudaGetSymbolAddress((void**)&w2t, g_W2t);

    const int n4 = M_ * K_GEMM / 4;
    dim3 split_grid((n4 + 255) / 256);
    dim3 prep_grid(N_GEMM / 32, K_GEMM / 32);
    dim3 prep_block(32, 8);
    dim3 gemm_grid(N_GEMM / 128, M_ / 128);   // (8, 32)

    // Q projection
    prep_w_kernel<<<prep_grid, prep_block>>>(WQ, w1t, w2t);
    split_bf16_kernel<<<split_grid, 256>>>(query, ahi, alo, n4);
    gemm_bf16x3_mma<<<gemm_grid, 256>>>(ahi, alo, w1t, w2t, bQ, gq);
    // K projection
    prep_w_kernel<<<prep_grid, prep_block>>>(WK, w1t, w2t);
    split_bf16_kernel<<<split_grid, 256>>>(key_, ahi, alo, n4);
    gemm_bf16x3_mma<<<gemm_grid, 256>>>(ahi, alo, w1t, w2t, bK, gk);
    // V projection
    prep_w_kernel<<<prep_grid, prep_block>>>(WV, w1t, w2t);
    split_bf16_kernel<<<split_grid, 256>>>(value, ahi, alo, n4);
    gemm_bf16x3_mma<<<gemm_grid, 256>>>(ahi, alo, w1t, w2t, bV, gv);

    // Attention
    dim3 attn_grid(S_ / 128, H_, B_);
    flash_attn_kernel<<<attn_grid, 128>>>(gq, gk, gv, gz);

    // Output projection
    prep_w_kernel<<<prep_grid, prep_block>>>(WO, w1t, w2t);
    split_bf16_kernel<<<split_grid, 256>>>(gz, ahi, alo, n4);
    gemm_bf16x3_mma<<<gemm_grid, 256>>>(ahi, alo, w1t, w2t, bO, out);
}

// round 4
// speedup vs baseline: 2.5960x; 2.0103x over previous
#include <cuda_runtime.h>
#include <cuda_bf16.h>
#include <cstdint>

// Problem constants
#define B_  2
#define S_  2048
#define E_  1024
#define H_  16
#define DH_ 64
#define HD_ 1024          // H*Dh
#define M_  (B_*S_)       // 4096 rows for all GEMMs
#define K_GEMM 1024
#define N_GEMM 1024

// ---------------------------------------------------------------------------
// Scratch (no cudaMalloc allowed)
// ---------------------------------------------------------------------------
__device__ __nv_bfloat16 g_Ahi[M_ * K_GEMM];      // split activations / Z
__device__ __nv_bfloat16 g_Alo[M_ * K_GEMM];
__device__ __nv_bfloat16 g_W1t[N_GEMM * K_GEMM];  // transposed+split weights [N][K]
__device__ __nv_bfloat16 g_W2t[N_GEMM * K_GEMM];
__device__ __nv_bfloat16 g_Qhi[M_ * HD_];
__device__ __nv_bfloat16 g_Qlo[M_ * HD_];
__device__ __nv_bfloat16 g_Khi[M_ * HD_];
__device__ __nv_bfloat16 g_Klo[M_ * HD_];
__device__ __nv_bfloat16 g_Vhi[M_ * HD_];
__device__ __nv_bfloat16 g_Vlo[M_ * HD_];

__device__ __forceinline__ uint32_t smem_u32(const void* p) {
    uint32_t a;
    asm("{ .reg .u64 t; cvta.to.shared.u64 t, %1; cvt.u32.u64 %0, t; }" : "=r"(a) : "l"(p));
    return a;
}
__device__ __forceinline__ float ex2f(float x) {
    float y;
    asm("ex2.approx.ftz.f32 %0, %1;" : "=f"(y) : "f"(x));
    return y;
}
__device__ __forceinline__ uint32_t pack_bf16(float a, float b) {
    __nv_bfloat162 t = __floats2bfloat162_rn(a, b);
    return *reinterpret_cast<uint32_t*>(&t);
}

#define LDSM4(r0, r1, r2, r3, addr) \
    asm volatile("ldmatrix.sync.aligned.m8n8.x4.shared.b16 {%0,%1,%2,%3}, [%4];" \
                 : "=r"(r0), "=r"(r1), "=r"(r2), "=r"(r3) : "r"(addr))
#define LDSM4T(r0, r1, r2, r3, addr) \
    asm volatile("ldmatrix.sync.aligned.m8n8.x4.trans.shared.b16 {%0,%1,%2,%3}, [%4];" \
                 : "=r"(r0), "=r"(r1), "=r"(r2), "=r"(r3) : "r"(addr))

#define MMA16816(d, a, b) \
    asm volatile("mma.sync.aligned.m16n8k16.row.col.f32.bf16.bf16.f32 " \
                 "{%0,%1,%2,%3}, {%4,%5,%6,%7}, {%8,%9}, {%0,%1,%2,%3};" \
                 : "+f"((d)[0]), "+f"((d)[1]), "+f"((d)[2]), "+f"((d)[3]) \
                 : "r"((a)[0]), "r"((a)[1]), "r"((a)[2]), "r"((a)[3]), \
                   "r"((b)[0]), "r"((b)[1]))

// ---------------------------------------------------------------------------
// Split fp32 -> (hi, lo) bf16, elementwise. n4 = elements/4.
// ---------------------------------------------------------------------------
__global__ void __launch_bounds__(256)
split_bf16_kernel(const float* __restrict__ x,
                  __nv_bfloat16* __restrict__ hi,
                  __nv_bfloat16* __restrict__ lo, int n4)
{
    int i = blockIdx.x * blockDim.x + threadIdx.x;
    if (i >= n4) return;
    float4 v = ((const float4*)x)[i];
    __nv_bfloat16 h0 = __float2bfloat16(v.x);
    __nv_bfloat16 h1 = __float2bfloat16(v.y);
    __nv_bfloat16 h2 = __float2bfloat16(v.z);
    __nv_bfloat16 h3 = __float2bfloat16(v.w);
    __nv_bfloat16 l0 = __float2bfloat16(v.x - __bfloat162float(h0));
    __nv_bfloat16 l1 = __float2bfloat16(v.y - __bfloat162float(h1));
    __nv_bfloat16 l2 = __float2bfloat16(v.z - __bfloat162float(h2));
    __nv_bfloat16 l3 = __float2bfloat16(v.w - __bfloat162float(h3));
    uint2 hp, lp;
    hp.x = pack_bf16(__bfloat162float(h0), __bfloat162float(h1));
    hp.y = pack_bf16(__bfloat162float(h2), __bfloat162float(h3));
    lp.x = pack_bf16(__bfloat162float(l0), __bfloat162float(l1));
    lp.y = pack_bf16(__bfloat162float(l2), __bfloat162float(l3));
    ((uint2*)hi)[i] = hp;
    ((uint2*)lo)[i] = lp;
}

// ---------------------------------------------------------------------------
// Weight prep: W[K][N] fp32 -> W1t/W2t [N][K] bf16 (transpose + split)
// ---------------------------------------------------------------------------
__global__ void __launch_bounds__(256)
prep_w_kernel(const float* __restrict__ W,
              __nv_bfloat16* __restrict__ w1t,
              __nv_bfloat16* __restrict__ w2t)
{
    __shared__ float t[32][33];
    int n0 = blockIdx.x * 32, k0 = blockIdx.y * 32;
    int tx = threadIdx.x, ty = threadIdx.y;
    #pragma unroll
    for (int i = 0; i < 4; i++)
        t[ty + 8 * i][tx] = W[(size_t)(k0 + ty + 8 * i) * N_GEMM + n0 + tx];
    __syncthreads();
    #pragma unroll
    for (int i = 0; i < 4; i++) {
        float v = t[tx][ty + 8 * i];
        __nv_bfloat16 h = __float2bfloat16(v);
        __nv_bfloat16 l = __float2bfloat16(v - __bfloat162float(h));
        size_t o = (size_t)(n0 + ty + 8 * i) * K_GEMM + k0 + tx;
        w1t[o] = h;
        w2t[o] = l;
    }
}

// ---------------------------------------------------------------------------
// HMMA bf16x3 GEMM: out = (Ahi+Alo) @ (W1t+W2t)^T + bias
// Epilogue either fp32 (Cf32 != null) or split hi/lo bf16 (Chi/Clo).
// ---------------------------------------------------------------------------
#define LDP 80
#define TILE_B (128 * LDP)

__global__ void __launch_bounds__(256)
gemm_bf16x3_mma(const __nv_bfloat16* __restrict__ Ahi,
                const __nv_bfloat16* __restrict__ Alo,
                const __nv_bfloat16* __restrict__ W1t,
                const __nv_bfloat16* __restrict__ W2t,
                const float* __restrict__ bias,
                float* __restrict__ Cf32,
                __nv_bfloat16* __restrict__ Chi,
                __nv_bfloat16* __restrict__ Clo)
{
    __shared__ __align__(16) char smem[4 * TILE_B];
    const uint32_t sb = smem_u32(smem);
    const uint32_t sA1 = sb, sA2 = sb + TILE_B, sW1 = sb + 2 * TILE_B, sW2 = sb + 3 * TILE_B;

    const int tid = threadIdx.x;
    const int wid = tid >> 5, lane = tid & 31;
    const int n0 = blockIdx.x * 128, m0 = blockIdx.y * 128;
    const int mw = (wid & 3) * 32;
    const int nw = (wid >> 2) * 64;

    float acc[2][8][4];
    #pragma unroll
    for (int mi = 0; mi < 2; mi++)
        #pragma unroll
        for (int ni = 0; ni < 8; ni++)
            #pragma unroll
            for (int r = 0; r < 4; r++) acc[mi][ni][r] = 0.f;

    const int row_[2] = { tid >> 2, (tid + 256) >> 2 };
    const int cc_[2]  = { tid & 3, (tid + 256) & 3 };

    const __nv_bfloat16* gA1 = Ahi + (size_t)m0 * K_GEMM;
    const __nv_bfloat16* gA2 = Alo + (size_t)m0 * K_GEMM;
    const __nv_bfloat16* gW1 = W1t + (size_t)n0 * K_GEMM;
    const __nv_bfloat16* gW2 = W2t + (size_t)n0 * K_GEMM;

    #pragma unroll
    for (int t = 0; t < 2; t++) {
        int row = row_[t], cc = cc_[t];
        size_t go = (size_t)row * K_GEMM + cc * 8;
        uint32_t so = row * LDP + cc * 16;
        *(float4*)(smem + 0 * TILE_B + so) = *(const float4*)&gA1[go];
        *(float4*)(smem + 1 * TILE_B + so) = *(const float4*)&gA2[go];
        *(float4*)(smem + 2 * TILE_B + so) = *(const float4*)&gW1[go];
        *(float4*)(smem + 3 * TILE_B + so) = *(const float4*)&gW2[go];
    }

    const uint32_t a_row = mw + (lane & 15);
    const uint32_t a_kadd = (lane >> 4) << 4;
    const uint32_t b_rowbase = nw + (lane & 7) + (((lane >> 4) & 1) << 3);
    const uint32_t b_kadd = ((lane >> 3) & 1) << 4;

    const int NCHUNK = K_GEMM / 32;
    float4 pf[4][2];

    for (int c = 0; c < NCHUNK; c++) {
        __syncthreads();

        if (c + 1 < NCHUNK) {
            int k0n = (c + 1) * 32;
            #pragma unroll
            for (int t = 0; t < 2; t++) {
                int row = row_[t], cc = cc_[t];
                size_t go = (size_t)row * K_GEMM + k0n + cc * 8;
                pf[0][t] = *(const float4*)&gA1[go];
                pf[1][t] = *(const float4*)&gA2[go];
                pf[2][t] = *(const float4*)&gW1[go];
                pf[3][t] = *(const float4*)&gW2[go];
            }
        }

        #pragma unroll
        for (int s = 0; s < 2; s++) {
            const uint32_t kb = s * 32;
            uint32_t a1f[2][4], a2f[2][4];
            #pragma unroll
            for (int mi = 0; mi < 2; mi++) {
                uint32_t addr1 = sA1 + (a_row + mi * 16) * LDP + kb + a_kadd;
                uint32_t addr2 = sA2 + (a_row + mi * 16) * LDP + kb + a_kadd;
                LDSM4(a1f[mi][0], a1f[mi][1], a1f[mi][2], a1f[mi][3], addr1);
                LDSM4(a2f[mi][0], a2f[mi][1], a2f[mi][2], a2f[mi][3], addr2);
            }
            uint32_t b1f[8][2], b2f[8][2];
            #pragma unroll
            for (int g = 0; g < 4; g++) {
                uint32_t addr1 = sW1 + (b_rowbase + g * 16) * LDP + kb + b_kadd;
                uint32_t addr2 = sW2 + (b_rowbase + g * 16) * LDP + kb + b_kadd;
                LDSM4(b1f[2*g][0], b1f[2*g][1], b1f[2*g+1][0], b1f[2*g+1][1], addr1);
                LDSM4(b2f[2*g][0], b2f[2*g][1], b2f[2*g+1][0], b2f[2*g+1][1], addr2);
            }
            #pragma unroll
            for (int mi = 0; mi < 2; mi++)
                #pragma unroll
                for (int ni = 0; ni < 8; ni++) {
                    MMA16816(acc[mi][ni], a1f[mi], b1f[ni]);
                    MMA16816(acc[mi][ni], a1f[mi], b2f[ni]);
                    MMA16816(acc[mi][ni], a2f[mi], b1f[ni]);
                }
        }

        __syncthreads();

        if (c + 1 < NCHUNK) {
            #pragma unroll
            for (int t = 0; t < 2; t++) {
                int row = row_[t], cc = cc_[t];
                uint32_t so = row * LDP + cc * 16;
                *(float4*)(smem + 0 * TILE_B + so) = pf[0][t];
                *(float4*)(smem + 1 * TILE_B + so) = pf[1][t];
                *(float4*)(smem + 2 * TILE_B + so) = pf[2][t];
                *(float4*)(smem + 3 * TILE_B + so) = pf[3][t];
            }
        }
    }

    const int erow = m0 + mw + (lane >> 2);
    const int ecol0 = n0 + nw + (lane & 3) * 2;
    #pragma unroll
    for (int mi = 0; mi < 2; mi++) {
        #pragma unroll
        for (int ni = 0; ni < 8; ni++) {
            int col = ecol0 + ni * 8;
            float b0 = bias[col], b1 = bias[col + 1];
            int r0 = erow + mi * 16;
            float v00 = acc[mi][ni][0] + b0, v01 = acc[mi][ni][1] + b1;
            float v10 = acc[mi][ni][2] + b0, v11 = acc[mi][ni][3] + b1;
            if (Cf32) {
                float2 w0 = { v00, v01 }, w1 = { v10, v11 };
                *(float2*)&Cf32[(size_t)r0 * N_GEMM + col] = w0;
                *(float2*)&Cf32[(size_t)(r0 + 8) * N_GEMM + col] = w1;
            } else {
                float h00 = __bfloat162float(__float2bfloat16(v00));
                float h01 = __bfloat162float(__float2bfloat16(v01));
                float h10 = __bfloat162float(__float2bfloat16(v10));
                float h11 = __bfloat162float(__float2bfloat16(v11));
                *(uint32_t*)&Chi[(size_t)r0 * N_GEMM + col] = pack_bf16(h00, h01);
                *(uint32_t*)&Chi[(size_t)(r0 + 8) * N_GEMM + col] = pack_bf16(h10, h11);
                *(uint32_t*)&Clo[(size_t)r0 * N_GEMM + col] = pack_bf16(v00 - h00, v01 - h01);
                *(uint32_t*)&Clo[(size_t)(r0 + 8) * N_GEMM + col] = pack_bf16(v10 - h10, v11 - h11);
            }
        }
    }
}

// ---------------------------------------------------------------------------
// HMMA flash attention, causal, bf16x3 compensated, online softmax (ex2 domain).
// CTA: 64 q rows, 4 warps (warp = m16). K/V tiles of 64 keys in SMEM (144B rows).
// grid (S/64, H, B), 128 threads.
// ---------------------------------------------------------------------------
#define LDK 144
#define SK_HI 0
#define SK_LO 9216
#define SV_HI 18432
#define SV_LO 27648

__global__ void __launch_bounds__(128)
flash_attn_mma(const __nv_bfloat16* __restrict__ Qhi, const __nv_bfloat16* __restrict__ Qlo,
               const __nv_bfloat16* __restrict__ Khi, const __nv_bfloat16* __restrict__ Klo,
               const __nv_bfloat16* __restrict__ Vhi, const __nv_bfloat16* __restrict__ Vlo,
               __nv_bfloat16* __restrict__ Zhi, __nv_bfloat16* __restrict__ Zlo)
{
    __shared__ __align__(16) char sm[36864];
    const uint32_t sb = smem_u32(sm);
    const int tid = threadIdx.x, wid = tid >> 5, lane = tid & 31;
    const int b = blockIdx.z, h = blockIdx.y, qt = blockIdx.x;
    const int q0 = qt * 64;
    const size_t hb = (size_t)b * S_ * HD_ + h * DH_;

    // Stage Q tile into K area, ldmatrix to registers.
    #pragma unroll
    for (int t = 0; t < 4; t++) {
        int idx = tid + t * 128; int row = idx >> 3, cc = idx & 7;
        size_t g = hb + (size_t)(q0 + row) * HD_ + cc * 8;
        *(float4*)(sm + SK_HI + row * LDK + cc * 16) = *(const float4*)&Qhi[g];
        *(float4*)(sm + SK_LO + row * LDK + cc * 16) = *(const float4*)&Qlo[g];
    }
    __syncthreads();

    uint32_t qh[4][4], ql[4][4];
    {
        const uint32_t arow = wid * 16 + (lane & 15);
        const uint32_t akadd = (lane >> 4) << 4;
        #pragma unroll
        for (int ks = 0; ks < 4; ks++) {
            uint32_t ah = sb + SK_HI + arow * LDK + ks * 32 + akadd;
            uint32_t al = sb + SK_LO + arow * LDK + ks * 32 + akadd;
            LDSM4(qh[ks][0], qh[ks][1], qh[ks][2], qh[ks][3], ah);
            LDSM4(ql[ks][0], ql[ks][1], ql[ks][2], ql[ks][3], al);
        }
    }

    float o[8][4];
    #pragma unroll
    for (int i = 0; i < 8; i++)
        #pragma unroll
        for (int j = 0; j < 4; j++) o[i][j] = 0.f;
    float m0 = -1e30f, m1 = -1e30f, l0 = 0.f, l1 = 0.f;

    const uint32_t browbase = (lane & 7) + (((lane >> 4) & 1) << 3);
    const uint32_t bkadd = ((lane >> 3) & 1) << 4;
    const uint32_t vrow = lane & 15;
    const uint32_t vnadd = (lane >> 4) << 4;
    const float alpha = 0.125f * 1.4426950408889634f;  // 1/sqrt(64) * log2(e)

    for (int kt = 0; kt <= qt; kt++) {
        __syncthreads();
        const int k0 = kt * 64;
        #pragma unroll
        for (int t = 0; t < 4; t++) {
            int idx = tid + t * 128; int row = idx >> 3, cc = idx & 7;
            size_t g = hb + (size_t)(k0 + row) * HD_ + cc * 8;
            uint32_t so = row * LDK + cc * 16;
            *(float4*)(sm + SK_HI + so) = *(const float4*)&Khi[g];
            *(float4*)(sm + SK_LO + so) = *(const float4*)&Klo[g];
            *(float4*)(sm + SV_HI + so) = *(const float4*)&Vhi[g];
            *(float4*)(sm + SV_LO + so) = *(const float4*)&Vlo[g];
        }
        __syncthreads();

        // S = Q K^T (3-term compensated)
        float s[8][4];
        #pragma unroll
        for (int i = 0; i < 8; i++)
            #pragma unroll
            for (int j = 0; j < 4; j++) s[i][j] = 0.f;
        #pragma unroll
        for (int ks = 0; ks < 4; ks++) {
            uint32_t kh[8][2], kl[8][2];
            #pragma unroll
            for (int g = 0; g < 4; g++) {
                uint32_t ah = sb + SK_HI + (browbase + g * 16) * LDK + ks * 32 + bkadd;
                uint32_t al = sb + SK_LO + (browbase + g * 16) * LDK + ks * 32 + bkadd;
                LDSM4(kh[2*g][0], kh[2*g][1], kh[2*g+1][0], kh[2*g+1][1], ah);
                LDSM4(kl[2*g][0], kl[2*g][1], kl[2*g+1][0], kl[2*g+1][1], al);
            }
            #pragma unroll
            for (int ni = 0; ni < 8; ni++) {
                MMA16816(s[ni], qh[ks], kh[ni]);
                MMA16816(s[ni], qh[ks], kl[ni]);
                MMA16816(s[ni], ql[ks], kh[ni]);
            }
        }

        // scale to log2 domain + causal mask on diagonal tile
        if (kt == qt) {
            const int rbase = wid * 16 + (lane >> 2);
            #pragma unroll
            for (int ni = 0; ni < 8; ni++) {
                int cb = ni * 8 + (lane & 3) * 2;
                s[ni][0] = (cb     <= rbase    ) ? s[ni][0] * alpha : -1e30f;
                s[ni][1] = (cb + 1 <= rbase    ) ? s[ni][1] * alpha : -1e30f;
                s[ni][2] = (cb     <= rbase + 8) ? s[ni][2] * alpha : -1e30f;
                s[ni][3] = (cb + 1 <= rbase + 8) ? s[ni][3] * alpha : -1e30f;
            }
        } else {
            #pragma unroll
            for (int ni = 0; ni < 8; ni++)
                #pragma unroll
                for (int j = 0; j < 4; j++) s[ni][j] *= alpha;
        }

        // online softmax
        float mx0 = m0, mx1 = m1;
        #pragma unroll
        for (int ni = 0; ni < 8; ni++) {
            mx0 = fmaxf(mx0, fmaxf(s[ni][0], s[ni][1]));
            mx1 = fmaxf(mx1, fmaxf(s[ni][2], s[ni][3]));
        }
        mx0 = fmaxf(mx0, __shfl_xor_sync(0xffffffffu, mx0, 1));
        mx0 = fmaxf(mx0, __shfl_xor_sync(0xffffffffu, mx0, 2));
        mx1 = fmaxf(mx1, __shfl_xor_sync(0xffffffffu, mx1, 1));
        mx1 = fmaxf(mx1, __shfl_xor_sync(0xffffffffu, mx1, 2));

        float sc0 = ex2f(m0 - mx0), sc1 = ex2f(m1 - mx1);
        l0 *= sc0; l1 *= sc1;
        #pragma unroll
        for (int ni = 0; ni < 8; ni++) {
            o[ni][0] *= sc0; o[ni][1] *= sc0;
            o[ni][2] *= sc1; o[ni][3] *= sc1;
        }
        m0 = mx0; m1 = mx1;

        // P = exp2(s - m), split hi/lo, build A-fragments
        uint32_t ph[4][4], pl[4][4];
        float rs0 = 0.f, rs1 = 0.f;
        #pragma unroll
        for (int ni = 0; ni < 8; ni++) {
            float p0 = ex2f(s[ni][0] - mx0);
            float p1 = ex2f(s[ni][1] - mx0);
            float p2 = ex2f(s[ni][2] - mx1);
            float p3 = ex2f(s[ni][3] - mx1);
            rs0 += p0 + p1; rs1 += p2 + p3;
            float h0 = __bfloat162float(__float2bfloat16(p0));
            float h1 = __bfloat162float(__float2bfloat16(p1));
            float h2 = __bfloat162float(__float2bfloat16(p2));
            float h3 = __bfloat162float(__float2bfloat16(p3));
            int kf = ni >> 1, hf = (ni & 1) * 2;
            ph[kf][hf + 0] = pack_bf16(h0, h1);
            ph[kf][hf + 1] = pack_bf16(h2, h3);
            pl[kf][hf + 0] = pack_bf16(p0 - h0, p1 - h1);
            pl[kf][hf + 1] = pack_bf16(p2 - h2, p3 - h3);
        }
        l0 += rs0; l1 += rs1;

        // O += P V (3-term compensated); V via ldmatrix.trans
        #pragma unroll
        for (int kf = 0; kf < 4; kf++) {
            uint32_t vh[8][2], vl[8][2];
            #pragma unroll
            for (int g = 0; g < 4; g++) {
                uint32_t ah = sb + SV_HI + (kf * 16 + vrow) * LDK + g * 32 + vnadd;
                uint32_t al = sb + SV_LO + (kf * 16 + vrow) * LDK + g * 32 + vnadd;
                LDSM4T(vh[2*g][0], vh[2*g][1], vh[2*g+1][0], vh[2*g+1][1], ah);
                LDSM4T(vl[2*g][0], vl[2*g][1], vl[2*g+1][0], vl[2*g+1][1], al);
            }
            #pragma unroll
            for (int nd = 0; nd < 8; nd++) {
                MMA16816(o[nd], ph[kf], vh[nd]);
                MMA16816(o[nd], ph[kf], vl[nd]);
                MMA16816(o[nd], pl[kf], vh[nd]);
            }
        }
    }

    // finalize: reduce l across lane quad, normalize, write Z as hi/lo bf16
    l0 += __shfl_xor_sync(0xffffffffu, l0, 1);
    l0 += __shfl_xor_sync(0xffffffffu, l0, 2);
    l1 += __shfl_xor_sync(0xffffffffu, l1, 1);
    l1 += __shfl_xor_sync(0xffffffffu, l1, 2);
    const float inv0 = 1.f / l0, inv1 = 1.f / l1;

    const int r0g = q0 + wid * 16 + (lane >> 2);
    const size_t z0 = hb + (size_t)r0g * HD_;
    const size_t z1 = z0 + (size_t)8 * HD_;
    #pragma unroll
    for (int nd = 0; nd < 8; nd++) {
        int col = nd * 8 + (lane & 3) * 2;
        float a0 = o[nd][0] * inv0, a1 = o[nd][1] * inv0;
        float b0 = o[nd][2] * inv1, b1 = o[nd][3] * inv1;
        float h00 = __bfloat162float(__float2bfloat16(a0));
        float h01 = __bfloat162float(__float2bfloat16(a1));
        float h10 = __bfloat162float(__float2bfloat16(b0));
        float h11 = __bfloat162float(__float2bfloat16(b1));
        *(uint32_t*)&Zhi[z0 + col] = pack_bf16(h00, h01);
        *(uint32_t*)&Zhi[z1 + col] = pack_bf16(h10, h11);
        *(uint32_t*)&Zlo[z0 + col] = pack_bf16(a0 - h00, a1 - h01);
        *(uint32_t*)&Zlo[z1 + col] = pack_bf16(b0 - h10, b1 - h11);
    }
}

// ---------------------------------------------------------------------------
// Launch
// ---------------------------------------------------------------------------
extern "C" void kernel_launch(void* const* d_in, const int* in_sizes, int n_in,
                              void* d_out, int out_size)
{
    const float* query = (const float*)d_in[0];
    const float* key_  = (const float*)d_in[1];
    const float* value = (const float*)d_in[2];
    const float* WQ = (const float*)d_in[4];
    const float* bQ = (const float*)d_in[5];
    const float* WK = (const float*)d_in[6];
    const float* bK = (const float*)d_in[7];
    const float* WV = (const float*)d_in[8];
    const float* bV = (const float*)d_in[9];
    const float* WO = (const float*)d_in[10];
    const float* bO = (const float*)d_in[11];
    float* out = (float*)d_out;

    __nv_bfloat16 *ahi, *alo, *w1t, *w2t, *qhi, *qlo, *khi, *klo, *vhi, *vlo;
    cudaGetSymbolAddress((void**)&ahi, g_Ahi);
    cudaGetSymbolAddress((void**)&alo, g_Alo);
    cudaGetSymbolAddress((void**)&w1t, g_W1t);
    cudaGetSymbolAddress((void**)&w2t, g_W2t);
    cudaGetSymbolAddress((void**)&qhi, g_Qhi);
    cudaGetSymbolAddress((void**)&qlo, g_Qlo);
    cudaGetSymbolAddress((void**)&khi, g_Khi);
    cudaGetSymbolAddress((void**)&klo, g_Klo);
    cudaGetSymbolAddress((void**)&vhi, g_Vhi);
    cudaGetSymbolAddress((void**)&vlo, g_Vlo);

    const int n4 = M_ * K_GEMM / 4;
    dim3 split_grid((n4 + 255) / 256);
    dim3 prep_grid(N_GEMM / 32, K_GEMM / 32);
    dim3 prep_block(32, 8);
    dim3 gemm_grid(N_GEMM / 128, M_ / 128);

    // Q projection -> hi/lo bf16
    prep_w_kernel<<<prep_grid, prep_block>>>(WQ, w1t, w2t);
    split_bf16_kernel<<<split_grid, 256>>>(query, ahi, alo, n4);
    gemm_bf16x3_mma<<<gemm_grid, 256>>>(ahi, alo, w1t, w2t, bQ, nullptr, qhi, qlo);
    // K projection
    prep_w_kernel<<<prep_grid, prep_block>>>(WK, w1t, w2t);
    split_bf16_kernel<<<split_grid, 256>>>(key_, ahi, alo, n4);
    gemm_bf16x3_mma<<<gemm_grid, 256>>>(ahi, alo, w1t, w2t, bK, nullptr, khi, klo);
    // V projection
    prep_w_kernel<<<prep_grid, prep_block>>>(WV, w1t, w2t);
    split_bf16_kernel<<<split_grid, 256>>>(value, ahi, alo, n4);
    gemm_bf16x3_mma<<<gemm_grid, 256>>>(ahi, alo, w1t, w2t, bV, nullptr, vhi, vlo);

    // Attention: writes Z hi/lo straight into the GEMM A buffers
    dim3 attn_grid(S_ / 64, H_, B_);
    flash_attn_mma<<<attn_grid, 128>>>(qhi, qlo, khi, klo, vhi, vlo, ahi, alo);

    // Output projection -> fp32 out
    prep_w_kernel<<<prep_grid, prep_block>>>(WO, w1t, w2t);
    gemm_bf16x3_mma<<<gemm_grid, 256>>>(ahi, alo, w1t, w2t, bO, out, nullptr, nullptr);
}

// round 5
// speedup vs baseline: 2.6540x; 1.0224x over previous
#include <cuda_runtime.h>
#include <cuda_bf16.h>
#include <cstdint>

// Problem constants
#define B_  2
#define S_  2048
#define E_  1024
#define H_  16
#define DH_ 64
#define HD_ 1024          // H*Dh
#define M_  (B_*S_)       // 4096 rows for all GEMMs
#define K_GEMM 1024
#define N_GEMM 1024

// ---------------------------------------------------------------------------
// Scratch (no cudaMalloc allowed)
// ---------------------------------------------------------------------------
__device__ __nv_bfloat16 g_Zhi[M_ * K_GEMM];          // attention output hi/lo
__device__ __nv_bfloat16 g_Zlo[M_ * K_GEMM];
__device__ __nv_bfloat16 g_W1t[4 * N_GEMM * K_GEMM];  // 4 transposed+split weights [N][K]
__device__ __nv_bfloat16 g_W2t[4 * N_GEMM * K_GEMM];
__device__ __nv_bfloat16 g_Qhi[M_ * HD_];
__device__ __nv_bfloat16 g_Qlo[M_ * HD_];
__device__ __nv_bfloat16 g_Khi[M_ * HD_];
__device__ __nv_bfloat16 g_Klo[M_ * HD_];
__device__ __nv_bfloat16 g_Vhi[M_ * HD_];
__device__ __nv_bfloat16 g_Vlo[M_ * HD_];

struct QkvArgs {
    const float* A[3];
    const float* bias[3];
    __nv_bfloat16* Ohi[3];
    __nv_bfloat16* Olo[3];
};
struct PrepArgs {
    const float* W[4];
};

__device__ __forceinline__ uint32_t smem_u32(const void* p) {
    uint32_t a;
    asm("{ .reg .u64 t; cvta.to.shared.u64 t, %1; cvt.u32.u64 %0, t; }" : "=r"(a) : "l"(p));
    return a;
}
__device__ __forceinline__ float ex2f(float x) {
    float y;
    asm("ex2.approx.ftz.f32 %0, %1;" : "=f"(y) : "f"(x));
    return y;
}
__device__ __forceinline__ uint32_t pack_bf16(float a, float b) {
    __nv_bfloat162 t = __floats2bfloat162_rn(a, b);
    return *reinterpret_cast<uint32_t*>(&t);
}
// split 8 fp32 -> 8 hi bf16 (16B) + 8 lo bf16 (16B)
__device__ __forceinline__ void cvt8(float4 a, float4 b, uint4& h4, uint4& l4) {
    float h0 = __bfloat162float(__float2bfloat16(a.x));
    float h1 = __bfloat162float(__float2bfloat16(a.y));
    float h2 = __bfloat162float(__float2bfloat16(a.z));
    float h3 = __bfloat162float(__float2bfloat16(a.w));
    float h4f = __bfloat162float(__float2bfloat16(b.x));
    float h5 = __bfloat162float(__float2bfloat16(b.y));
    float h6 = __bfloat162float(__float2bfloat16(b.z));
    float h7 = __bfloat162float(__float2bfloat16(b.w));
    h4.x = pack_bf16(h0, h1);  h4.y = pack_bf16(h2, h3);
    h4.z = pack_bf16(h4f, h5); h4.w = pack_bf16(h6, h7);
    l4.x = pack_bf16(a.x - h0, a.y - h1);
    l4.y = pack_bf16(a.z - h2, a.w - h3);
    l4.z = pack_bf16(b.x - h4f, b.y - h5);
    l4.w = pack_bf16(b.z - h6, b.w - h7);
}

#define LDSM4(r0, r1, r2, r3, addr) \
    asm volatile("ldmatrix.sync.aligned.m8n8.x4.shared.b16 {%0,%1,%2,%3}, [%4];" \
                 : "=r"(r0), "=r"(r1), "=r"(r2), "=r"(r3) : "r"(addr))
#define LDSM4T(r0, r1, r2, r3, addr) \
    asm volatile("ldmatrix.sync.aligned.m8n8.x4.trans.shared.b16 {%0,%1,%2,%3}, [%4];" \
                 : "=r"(r0), "=r"(r1), "=r"(r2), "=r"(r3) : "r"(addr))
#define MMA16816(d, a, b) \
    asm volatile("mma.sync.aligned.m16n8k16.row.col.f32.bf16.bf16.f32 " \
                 "{%0,%1,%2,%3}, {%4,%5,%6,%7}, {%8,%9}, {%0,%1,%2,%3};" \
                 : "+f"((d)[0]), "+f"((d)[1]), "+f"((d)[2]), "+f"((d)[3]) \
                 : "r"((a)[0]), "r"((a)[1]), "r"((a)[2]), "r"((a)[3]), \
                   "r"((b)[0]), "r"((b)[1]))

// ---------------------------------------------------------------------------
// Weight prep (batched): W[K][N] fp32 -> W1t/W2t[z] [N][K] bf16 (transpose+split)
// grid (N/32, K/32, 4), block (32,8)
// ---------------------------------------------------------------------------
__global__ void __launch_bounds__(256)
prep_w_kernel(PrepArgs pa,
              __nv_bfloat16* __restrict__ w1t,
              __nv_bfloat16* __restrict__ w2t)
{
    __shared__ float t[32][33];
    const float* W = pa.W[blockIdx.z];
    const size_t zoff = (size_t)blockIdx.z * N_GEMM * K_GEMM;
    int n0 = blockIdx.x * 32, k0 = blockIdx.y * 32;
    int tx = threadIdx.x, ty = threadIdx.y;
    #pragma unroll
    for (int i = 0; i < 4; i++)
        t[ty + 8 * i][tx] = W[(size_t)(k0 + ty + 8 * i) * N_GEMM + n0 + tx];
    __syncthreads();
    #pragma unroll
    for (int i = 0; i < 4; i++) {
        float v = t[tx][ty + 8 * i];
        __nv_bfloat16 h = __float2bfloat16(v);
        __nv_bfloat16 l = __float2bfloat16(v - __bfloat162float(h));
        size_t o = zoff + (size_t)(n0 + ty + 8 * i) * K_GEMM + k0 + tx;
        w1t[o] = h;
        w2t[o] = l;
    }
}

// ---------------------------------------------------------------------------
// HMMA bf16x3 GEMM, two modes:
//  MODE 0 (QKV, grid.z=3): A = fp32 (split to hi/lo inline), out = hi/lo bf16
//  MODE 1 (O-proj): A = hi/lo bf16, out = fp32
// CTA 128x128, BK=32, 8 warps (4M x 2N), register-prefetch pipeline.
// ---------------------------------------------------------------------------
#define LDP 80
#define TILE_B (128 * LDP)

template<int MODE>
__global__ void __launch_bounds__(256)
gemm_bf16x3_mma(QkvArgs qa,
                const __nv_bfloat16* __restrict__ Ahi,
                const __nv_bfloat16* __restrict__ Alo,
                const __nv_bfloat16* __restrict__ W1base,
                const __nv_bfloat16* __restrict__ W2base,
                const float* __restrict__ biasO,
                float* __restrict__ Cout)
{
    __shared__ __align__(16) char smem[4 * TILE_B];   // A1 | A2 | W1 | W2
    const uint32_t sb = smem_u32(smem);
    const uint32_t sA1 = sb, sA2 = sb + TILE_B, sW1 = sb + 2 * TILE_B, sW2 = sb + 3 * TILE_B;

    const int z = blockIdx.z;
    const int tid = threadIdx.x;
    const int wid = tid >> 5, lane = tid & 31;
    const int n0 = blockIdx.x * 128, m0 = blockIdx.y * 128;
    const int mw = (wid & 3) * 32;
    const int nw = (wid >> 2) * 64;

    const size_t woff = (MODE == 0 ? (size_t)z : (size_t)3) * N_GEMM * K_GEMM;
    const __nv_bfloat16* gW1 = W1base + woff + (size_t)n0 * K_GEMM;
    const __nv_bfloat16* gW2 = W2base + woff + (size_t)n0 * K_GEMM;
    const float* gAf = (MODE == 0) ? qa.A[z] + (size_t)m0 * K_GEMM : nullptr;
    const __nv_bfloat16* gA1 = (MODE == 1) ? Ahi + (size_t)m0 * K_GEMM : nullptr;
    const __nv_bfloat16* gA2 = (MODE == 1) ? Alo + (size_t)m0 * K_GEMM : nullptr;

    float acc[2][8][4];
    #pragma unroll
    for (int mi = 0; mi < 2; mi++)
        #pragma unroll
        for (int ni = 0; ni < 8; ni++)
            #pragma unroll
            for (int r = 0; r < 4; r++) acc[mi][ni][r] = 0.f;

    const int row_[2] = { tid >> 2, (tid + 256) >> 2 };
    const int cc_[2]  = { tid & 3, (tid + 256) & 3 };

    // ---- load chunk 0 ----
    #pragma unroll
    for (int t = 0; t < 2; t++) {
        int row = row_[t], cc = cc_[t];
        uint32_t so = row * LDP + cc * 16;
        if (MODE == 0) {
            size_t go = (size_t)row * K_GEMM + cc * 8;
            float4 fa = *(const float4*)&gAf[go];
            float4 fb = *(const float4*)&gAf[go + 4];
            uint4 h4, l4; cvt8(fa, fb, h4, l4);
            *(uint4*)(smem + 0 * TILE_B + so) = h4;
            *(uint4*)(smem + 1 * TILE_B + so) = l4;
        } else {
            size_t go = (size_t)row * K_GEMM + cc * 8;
            *(float4*)(smem + 0 * TILE_B + so) = *(const float4*)&gA1[go];
            *(float4*)(smem + 1 * TILE_B + so) = *(const float4*)&gA2[go];
        }
        size_t gw = (size_t)row * K_GEMM + cc * 8;
        *(float4*)(smem + 2 * TILE_B + so) = *(const float4*)&gW1[gw];
        *(float4*)(smem + 3 * TILE_B + so) = *(const float4*)&gW2[gw];
    }

    const uint32_t a_row = mw + (lane & 15);
    const uint32_t a_kadd = (lane >> 4) << 4;
    const uint32_t b_rowbase = nw + (lane & 7) + (((lane >> 4) & 1) << 3);
    const uint32_t b_kadd = ((lane >> 3) & 1) << 4;

    const int NCHUNK = K_GEMM / 32;
    float4 pfa[2][2];    // fp32 A prefetch (mode 0) or A1/A2 bf16 (mode 1)
    float4 pfw[2][2];

    for (int c = 0; c < NCHUNK; c++) {
        __syncthreads();

        if (c + 1 < NCHUNK) {
            int k0n = (c + 1) * 32;
            #pragma unroll
            for (int t = 0; t < 2; t++) {
                int row = row_[t], cc = cc_[t];
                if (MODE == 0) {
                    size_t go = (size_t)row * K_GEMM + k0n + cc * 8;
                    pfa[0][t] = *(const float4*)&gAf[go];
                    pfa[1][t] = *(const float4*)&gAf[go + 4];
                } else {
                    size_t go = (size_t)row * K_GEMM + k0n + cc * 8;
                    pfa[0][t] = *(const float4*)&gA1[go];
                    pfa[1][t] = *(const float4*)&gA2[go];
                }
                size_t gw = (size_t)row * K_GEMM + k0n + cc * 8;
                pfw[0][t] = *(const float4*)&gW1[gw];
                pfw[1][t] = *(const float4*)&gW2[gw];
            }
        }

        #pragma unroll
        for (int s = 0; s < 2; s++) {
            const uint32_t kb = s * 32;
            uint32_t a1f[2][4], a2f[2][4];
            #pragma unroll
            for (int mi = 0; mi < 2; mi++) {
                uint32_t addr1 = sA1 + (a_row + mi * 16) * LDP + kb + a_kadd;
                uint32_t addr2 = sA2 + (a_row + mi * 16) * LDP + kb + a_kadd;
                LDSM4(a1f[mi][0], a1f[mi][1], a1f[mi][2], a1f[mi][3], addr1);
                LDSM4(a2f[mi][0], a2f[mi][1], a2f[mi][2], a2f[mi][3], addr2);
            }
            uint32_t b1f[8][2], b2f[8][2];
            #pragma unroll
            for (int g = 0; g < 4; g++) {
                uint32_t addr1 = sW1 + (b_rowbase + g * 16) * LDP + kb + b_kadd;
                uint32_t addr2 = sW2 + (b_rowbase + g * 16) * LDP + kb + b_kadd;
                LDSM4(b1f[2*g][0], b1f[2*g][1], b1f[2*g+1][0], b1f[2*g+1][1], addr1);
                LDSM4(b2f[2*g][0], b2f[2*g][1], b2f[2*g+1][0], b2f[2*g+1][1], addr2);
            }
            #pragma unroll
            for (int mi = 0; mi < 2; mi++)
                #pragma unroll
                for (int ni = 0; ni < 8; ni++) {
                    MMA16816(acc[mi][ni], a1f[mi], b1f[ni]);
                    MMA16816(acc[mi][ni], a1f[mi], b2f[ni]);
                    MMA16816(acc[mi][ni], a2f[mi], b1f[ni]);
                }
        }

        __syncthreads();

        if (c + 1 < NCHUNK) {
            #pragma unroll
            for (int t = 0; t < 2; t++) {
                int row = row_[t], cc = cc_[t];
                uint32_t so = row * LDP + cc * 16;
                if (MODE == 0) {
                    uint4 h4, l4; cvt8(pfa[0][t], pfa[1][t], h4, l4);
                    *(uint4*)(smem + 0 * TILE_B + so) = h4;
                    *(uint4*)(smem + 1 * TILE_B + so) = l4;
                } else {
                    *(float4*)(smem + 0 * TILE_B + so) = pfa[0][t];
                    *(float4*)(smem + 1 * TILE_B + so) = pfa[1][t];
                }
                *(float4*)(smem + 2 * TILE_B + so) = pfw[0][t];
                *(float4*)(smem + 3 * TILE_B + so) = pfw[1][t];
            }
        }
    }

    // ---- epilogue ----
    const float* bias = (MODE == 0) ? qa.bias[z] : biasO;
    const int erow = m0 + mw + (lane >> 2);
    const int ecol0 = n0 + nw + (lane & 3) * 2;
    #pragma unroll
    for (int mi = 0; mi < 2; mi++) {
        #pragma unroll
        for (int ni = 0; ni < 8; ni++) {
            int col = ecol0 + ni * 8;
            float b0 = bias[col], b1 = bias[col + 1];
            int r0 = erow + mi * 16;
            float v00 = acc[mi][ni][0] + b0, v01 = acc[mi][ni][1] + b1;
            float v10 = acc[mi][ni][2] + b0, v11 = acc[mi][ni][3] + b1;
            if (MODE == 1) {
                float2 w0 = { v00, v01 }, w1 = { v10, v11 };
                *(float2*)&Cout[(size_t)r0 * N_GEMM + col] = w0;
                *(float2*)&Cout[(size_t)(r0 + 8) * N_GEMM + col] = w1;
            } else {
                __nv_bfloat16* Chi = qa.Ohi[z];
                __nv_bfloat16* Clo = qa.Olo[z];
                float h00 = __bfloat162float(__float2bfloat16(v00));
                float h01 = __bfloat162float(__float2bfloat16(v01));
                float h10 = __bfloat162float(__float2bfloat16(v10));
                float h11 = __bfloat162float(__float2bfloat16(v11));
                *(uint32_t*)&Chi[(size_t)r0 * N_GEMM + col] = pack_bf16(h00, h01);
                *(uint32_t*)&Chi[(size_t)(r0 + 8) * N_GEMM + col] = pack_bf16(h10, h11);
                *(uint32_t*)&Clo[(size_t)r0 * N_GEMM + col] = pack_bf16(v00 - h00, v01 - h01);
                *(uint32_t*)&Clo[(size_t)(r0 + 8) * N_GEMM + col] = pack_bf16(v10 - h10, v11 - h11);
            }
        }
    }
}

// ---------------------------------------------------------------------------
// HMMA flash attention, causal, bf16x3, online softmax (ex2 domain).
// CTA: 128 q rows, 8 warps (warp = m16). K/V tiles of 64 keys in SMEM.
// grid (S/128, H, B), 256 threads.
// ---------------------------------------------------------------------------
#define LDK 144
#define SK_HI 0
#define SK_LO 9216
#define SV_HI 18432
#define SV_LO 27648
#define SQ    18432     // Q staged through V area (128 rows x 144B = 18432B)

__global__ void __launch_bounds__(256)
flash_attn_mma(const __nv_bfloat16* __restrict__ Qhi, const __nv_bfloat16* __restrict__ Qlo,
               const __nv_bfloat16* __restrict__ Khi, const __nv_bfloat16* __restrict__ Klo,
               const __nv_bfloat16* __restrict__ Vhi, const __nv_bfloat16* __restrict__ Vlo,
               __nv_bfloat16* __restrict__ Zhi, __nv_bfloat16* __restrict__ Zlo)
{
    __shared__ __align__(16) char sm[36864];
    const uint32_t sb = smem_u32(sm);
    const int tid = threadIdx.x, wid = tid >> 5, lane = tid & 31;
    const int b = blockIdx.z, h = blockIdx.y, qt = blockIdx.x;
    const int q0 = qt * 128;
    const size_t hb = (size_t)b * S_ * HD_ + h * DH_;

    const uint32_t arow = wid * 16 + (lane & 15);
    const uint32_t akadd = (lane >> 4) << 4;

    // Stage Qhi then Qlo through the V area, ldmatrix into registers.
    uint32_t qh[4][4], ql[4][4];
    #pragma unroll
    for (int t = 0; t < 4; t++) {
        int idx = tid + t * 256; int row = idx >> 3, cc = idx & 7;
        *(float4*)(sm + SQ + row * LDK + cc * 16) =
            *(const float4*)&Qhi[hb + (size_t)(q0 + row) * HD_ + cc * 8];
    }
    __syncthreads();
    #pragma unroll
    for (int ks = 0; ks < 4; ks++) {
        uint32_t a = sb + SQ + arow * LDK + ks * 32 + akadd;
        LDSM4(qh[ks][0], qh[ks][1], qh[ks][2], qh[ks][3], a);
    }
    __syncthreads();
    #pragma unroll
    for (int t = 0; t < 4; t++) {
        int idx = tid + t * 256; int row = idx >> 3, cc = idx & 7;
        *(float4*)(sm + SQ + row * LDK + cc * 16) =
            *(const float4*)&Qlo[hb + (size_t)(q0 + row) * HD_ + cc * 8];
    }
    __syncthreads();
    #pragma unroll
    for (int ks = 0; ks < 4; ks++) {
        uint32_t a = sb + SQ + arow * LDK + ks * 32 + akadd;
        LDSM4(ql[ks][0], ql[ks][1], ql[ks][2], ql[ks][3], a);
    }

    float o[8][4];
    #pragma unroll
    for (int i = 0; i < 8; i++)
        #pragma unroll
        for (int j = 0; j < 4; j++) o[i][j] = 0.f;
    float m0 = -1e30f, m1 = -1e30f, l0 = 0.f, l1 = 0.f;

    const uint32_t browbase = (lane & 7) + (((lane >> 4) & 1) << 3);
    const uint32_t bkadd = ((lane >> 3) & 1) << 4;
    const uint32_t vrow = lane & 15;
    const uint32_t vnadd = (lane >> 4) << 4;
    const float alpha = 0.125f * 1.4426950408889634f;  // 1/sqrt(64) * log2(e)
    const int rowg = q0 + wid * 16 + (lane >> 2);      // this thread's first q row

    const int nt = 2 * qt + 2;
    for (int kt = 0; kt < nt; kt++) {
        __syncthreads();
        const int k0 = kt * 64;
        #pragma unroll
        for (int t = 0; t < 2; t++) {
            int idx = tid + t * 256; int row = idx >> 3, cc = idx & 7;
            size_t g = hb + (size_t)(k0 + row) * HD_ + cc * 8;
            uint32_t so = row * LDK + cc * 16;
            *(float4*)(sm + SK_HI + so) = *(const float4*)&Khi[g];
            *(float4*)(sm + SK_LO + so) = *(const float4*)&Klo[g];
            *(float4*)(sm + SV_HI + so) = *(const float4*)&Vhi[g];
            *(float4*)(sm + SV_LO + so) = *(const float4*)&Vlo[g];
        }
        __syncthreads();

        // S = Q K^T (3-term compensated)
        float s[8][4];
        #pragma unroll
        for (int i = 0; i < 8; i++)
            #pragma unroll
            for (int j = 0; j < 4; j++) s[i][j] = 0.f;
        #pragma unroll
        for (int ks = 0; ks < 4; ks++) {
            uint32_t kh[8][2], kl[8][2];
            #pragma unroll
            for (int g = 0; g < 4; g++) {
                uint32_t ah = sb + SK_HI + (browbase + g * 16) * LDK + ks * 32 + bkadd;
                uint32_t al = sb + SK_LO + (browbase + g * 16) * LDK + ks * 32 + bkadd;
                LDSM4(kh[2*g][0], kh[2*g][1], kh[2*g+1][0], kh[2*g+1][1], ah);
                LDSM4(kl[2*g][0], kl[2*g][1], kl[2*g+1][0], kl[2*g+1][1], al);
            }
            #pragma unroll
            for (int ni = 0; ni < 8; ni++) {
                MMA16816(s[ni], qh[ks], kh[ni]);
                MMA16816(s[ni], qh[ks], kl[ni]);
                MMA16816(s[ni], ql[ks], kh[ni]);
            }
        }

        // scale to log2 domain + causal mask (only if this warp band intersects)
        if (k0 + 63 > q0 + wid * 16) {
            #pragma unroll
            for (int ni = 0; ni < 8; ni++) {
                int colg = k0 + ni * 8 + (lane & 3) * 2;
                s[ni][0] = (colg     <= rowg    ) ? s[ni][0] * alpha : -1e30f;
                s[ni][1] = (colg + 1 <= rowg    ) ? s[ni][1] * alpha : -1e30f;
                s[ni][2] = (colg     <= rowg + 8) ? s[ni][2] * alpha : -1e30f;
                s[ni][3] = (colg + 1 <= rowg + 8) ? s[ni][3] * alpha : -1e30f;
            }
        } else {
            #pragma unroll
            for (int ni = 0; ni < 8; ni++)
                #pragma unroll
                for (int j = 0; j < 4; j++) s[ni][j] *= alpha;
        }

        // online softmax
        float mx0 = m0, mx1 = m1;
        #pragma unroll
        for (int ni = 0; ni < 8; ni++) {
            mx0 = fmaxf(mx0, fmaxf(s[ni][0], s[ni][1]));
            mx1 = fmaxf(mx1, fmaxf(s[ni][2], s[ni][3]));
        }
        mx0 = fmaxf(mx0, __shfl_xor_sync(0xffffffffu, mx0, 1));
        mx0 = fmaxf(mx0, __shfl_xor_sync(0xffffffffu, mx0, 2));
        mx1 = fmaxf(mx1, __shfl_xor_sync(0xffffffffu, mx1, 1));
        mx1 = fmaxf(mx1, __shfl_xor_sync(0xffffffffu, mx1, 2));

        float sc0 = ex2f(m0 - mx0), sc1 = ex2f(m1 - mx1);
        l0 *= sc0; l1 *= sc1;
        #pragma unroll
        for (int ni = 0; ni < 8; ni++) {
            o[ni][0] *= sc0; o[ni][1] *= sc0;
            o[ni][2] *= sc1; o[ni][3] *= sc1;
        }
        m0 = mx0; m1 = mx1;

        // P = exp2(s - m), split hi/lo
        uint32_t ph[4][4], pl[4][4];
        float rs0 = 0.f, rs1 = 0.f;
        #pragma unroll
        for (int ni = 0; ni < 8; ni++) {
            float p0 = ex2f(s[ni][0] - mx0);
            float p1 = ex2f(s[ni][1] - mx0);
            float p2 = ex2f(s[ni][2] - mx1);
            float p3 = ex2f(s[ni][3] - mx1);
            rs0 += p0 + p1; rs1 += p2 + p3;
            float h0 = __bfloat162float(__float2bfloat16(p0));
            float h1 = __bfloat162float(__float2bfloat16(p1));
            float h2 = __bfloat162float(__float2bfloat16(p2));
            float h3 = __bfloat162float(__float2bfloat16(p3));
            int kf = ni >> 1, hf = (ni & 1) * 2;
            ph[kf][hf + 0] = pack_bf16(h0, h1);
            ph[kf][hf + 1] = pack_bf16(h2, h3);
            pl[kf][hf + 0] = pack_bf16(p0 - h0, p1 - h1);
            pl[kf][hf + 1] = pack_bf16(p2 - h2, p3 - h3);
        }
        l0 += rs0; l1 += rs1;

        // O += P V (3-term); V via ldmatrix.trans
        #pragma unroll
        for (int kf = 0; kf < 4; kf++) {
            uint32_t vh[8][2], vl[8][2];
            #pragma unroll
            for (int g = 0; g < 4; g++) {
                uint32_t ah = sb + SV_HI + (kf * 16 + vrow) * LDK + g * 32 + vnadd;
                uint32_t al = sb + SV_LO + (kf * 16 + vrow) * LDK + g * 32 + vnadd;
                LDSM4T(vh[2*g][0], vh[2*g][1], vh[2*g+1][0], vh[2*g+1][1], ah);
                LDSM4T(vl[2*g][0], vl[2*g][1], vl[2*g+1][0], vl[2*g+1][1], al);
            }
            #pragma unroll
            for (int nd = 0; nd < 8; nd++) {
                MMA16816(o[nd], ph[kf], vh[nd]);
                MMA16816(o[nd], ph[kf], vl[nd]);
                MMA16816(o[nd], pl[kf], vh[nd]);
            }
        }
    }

    // finalize
    l0 += __shfl_xor_sync(0xffffffffu, l0, 1);
    l0 += __shfl_xor_sync(0xffffffffu, l0, 2);
    l1 += __shfl_xor_sync(0xffffffffu, l1, 1);
    l1 += __shfl_xor_sync(0xffffffffu, l1, 2);
    const float inv0 = 1.f / l0, inv1 = 1.f / l1;

    const size_t z0 = hb + (size_t)rowg * HD_;
    const size_t z1 = z0 + (size_t)8 * HD_;
    #pragma unroll
    for (int nd = 0; nd < 8; nd++) {
        int col = nd * 8 + (lane & 3) * 2;
        float a0 = o[nd][0] * inv0, a1 = o[nd][1] * inv0;
        float b0 = o[nd][2] * inv1, b1 = o[nd][3] * inv1;
        float h00 = __bfloat162float(__float2bfloat16(a0));
        float h01 = __bfloat162float(__float2bfloat16(a1));
        float h10 = __bfloat162float(__float2bfloat16(b0));
        float h11 = __bfloat162float(__float2bfloat16(b1));
        *(uint32_t*)&Zhi[z0 + col] = pack_bf16(h00, h01);
        *(uint32_t*)&Zhi[z1 + col] = pack_bf16(h10, h11);
        *(uint32_t*)&Zlo[z0 + col] = pack_bf16(a0 - h00, a1 - h01);
        *(uint32_t*)&Zlo[z1 + col] = pack_bf16(b0 - h10, b1 - h11);
    }
}

// ---------------------------------------------------------------------------
// Launch
// ---------------------------------------------------------------------------
extern "C" void kernel_launch(void* const* d_in, const int* in_sizes, int n_in,
                              void* d_out, int out_size)
{
    const float* query = (const float*)d_in[0];
    const float* key_  = (const float*)d_in[1];
    const float* value = (const float*)d_in[2];
    const float* WQ = (const float*)d_in[4];
    const float* bQ = (const float*)d_in[5];
    const float* WK = (const float*)d_in[6];
    const float* bK = (const float*)d_in[7];
    const float* WV = (const float*)d_in[8];
    const float* bV = (const float*)d_in[9];
    const float* WO = (const float*)d_in[10];
    const float* bO = (const float*)d_in[11];
    float* out = (float*)d_out;

    __nv_bfloat16 *zhi, *zlo, *w1t, *w2t, *qhi, *qlo, *khi, *klo, *vhi, *vlo;
    cudaGetSymbolAddress((void**)&zhi, g_Zhi);
    cudaGetSymbolAddress((void**)&zlo, g_Zlo);
    cudaGetSymbolAddress((void**)&w1t, g_W1t);
    cudaGetSymbolAddress((void**)&w2t, g_W2t);
    cudaGetSymbolAddress((void**)&qhi, g_Qhi);
    cudaGetSymbolAddress((void**)&qlo, g_Qlo);
    cudaGetSymbolAddress((void**)&khi, g_Khi);
    cudaGetSymbolAddress((void**)&klo, g_Klo);
    cudaGetSymbolAddress((void**)&vhi, g_Vhi);
    cudaGetSymbolAddress((void**)&vlo, g_Vlo);

    PrepArgs pp;
    pp.W[0] = WQ; pp.W[1] = WK; pp.W[2] = WV; pp.W[3] = WO;

    QkvArgs qa;
    qa.A[0] = query; qa.A[1] = key_; qa.A[2] = value;
    qa.bias[0] = bQ; qa.bias[1] = bK; qa.bias[2] = bV;
    qa.Ohi[0] = qhi; qa.Ohi[1] = khi; qa.Ohi[2] = vhi;
    qa.Olo[0] = qlo; qa.Olo[1] = klo; qa.Olo[2] = vlo;

    // 1. All weight preps (one launch)
    prep_w_kernel<<<dim3(N_GEMM / 32, K_GEMM / 32, 4), dim3(32, 8)>>>(pp, w1t, w2t);

    // 2. QKV projections (one launch, grid.z = 3), fp32 A split inline
    gemm_bf16x3_mma<0><<<dim3(N_GEMM / 128, M_ / 128, 3), 256>>>(
        qa, nullptr, nullptr, w1t, w2t, nullptr, nullptr);

    // 3. Flash attention (q-tile 128), writes Z hi/lo
    flash_attn_mma<<<dim3(S_ / 128, H_, B_), 256>>>(
        qhi, qlo, khi, klo, vhi, vlo, zhi, zlo);

    // 4. Output projection -> fp32 out
    gemm_bf16x3_mma<1><<<dim3(N_GEMM / 128, M_ / 128, 1), 256>>>(
        qa, zhi, zlo, w1t, w2t, bO, out);
}